// round 6
// baseline (speedup 1.0000x reference)
#include <cuda_runtime.h>
#include <cuda_bf16.h>
#include <cstdint>
#include <cstring>

#define DD 1024
#define MM 256
#define BB 2048
#define NT 1024      // tiles: 64b x 16m x 512d  (32 bT x 16 mT x 2 dH)
#define CHUNKS 16    // chunks per tile, 32 d each
#define NCTA 296     // 2 x 148 SMs

// Device scratch (no allocations allowed)
__device__ __align__(16) uint32_t g_cb[MM * DD];           // per d-pair: {c1 bf16x2, c0 bf16x2}
__device__ __align__(16) uint32_t g_xb[BB * (DD / 2)];     // x as bf16x2 pairs
__device__ __align__(16) float g_logw[MM];
__device__ __align__(16) float g_part[2][BB * MM];         // per d-half partial log2 sums
__device__ int g_ctr;

__device__ __forceinline__ __nv_bfloat162 asbf2(uint32_t u) {
    __nv_bfloat162 r; memcpy(&r, &u, 4); return r;
}
__device__ __forceinline__ uint32_t asu32(__nv_bfloat162 b) {
    uint32_t u; memcpy(&u, &b, 4); return u;
}
__device__ __forceinline__ void cp16(uint32_t dst, const void* src) {
    asm volatile("cp.async.ca.shared.global [%0], [%1], 16;" :: "r"(dst), "l"(src));
}

// ---------------------------------------------------------------------------
// Fused prep: blocks [0,512) x->bf16 (MLP4); [512,640) P->coefs (MLP4);
// block 640: logw + tile-counter reset.
// ---------------------------------------------------------------------------
__global__ void prep_kernel(const float* __restrict__ x,
                            const float* __restrict__ P,
                            const float* __restrict__ W) {
    int bk = blockIdx.x, t = threadIdx.x;
    if (bk < 512) {
        const float4* src = reinterpret_cast<const float4*>(x) + bk * 1024 + t;
        uint2* dst = reinterpret_cast<uint2*>(g_xb) + bk * 1024 + t;
        float4 v[4];
#pragma unroll
        for (int k = 0; k < 4; k++) v[k] = src[k * 256];
#pragma unroll
        for (int k = 0; k < 4; k++) {
            uint2 w;
            w.x = asu32(__floats2bfloat162_rn(v[k].x, v[k].y));
            w.y = asu32(__floats2bfloat162_rn(v[k].z, v[k].w));
            dst[k * 256] = w;
        }
    } else if (bk < 640) {
        int b2 = bk - 512;
        const float2* src = reinterpret_cast<const float2*>(P) + b2 * 1024 + t;
        uint2* dst = reinterpret_cast<uint2*>(g_cb) + b2 * 1024 + t;
        float2 v[4];
#pragma unroll
        for (int k = 0; k < 4; k++) v[k] = src[k * 256];
#pragma unroll
        for (int k = 0; k < 4; k++) {
            float c0a = 2.0f / (1.0f + __expf(v[k].x));   // 2*(1-p)
            float c0b = 2.0f / (1.0f + __expf(v[k].y));
            float c1a = 2.0f - 2.0f * c0a;                // 2*(2p-1)
            float c1b = 2.0f - 2.0f * c0b;
            uint2 w;
            w.x = asu32(__floats2bfloat162_rn(c1a, c1b));
            w.y = asu32(__floats2bfloat162_rn(c0a, c0b));
            dst[k * 256] = w;
        }
    } else {
        __shared__ float sh[MM];
        float w = W[t];
        sh[t] = w;
        __syncthreads();
        for (int s = MM / 2; s > 0; s >>= 1) {
            if (t < s) sh[t] = fmaxf(sh[t], sh[t + s]);
            __syncthreads();
        }
        float mx = sh[0];
        __syncthreads();
        sh[t] = expf(w - mx);
        __syncthreads();
        for (int s = MM / 2; s > 0; s >>= 1) {
            if (t < s) sh[t] += sh[t + s];
            __syncthreads();
        }
        g_logw[t] = w - (mx + logf(sh[0]));
        if (t == 0) g_ctr = NCTA;
    }
}

// ---------------------------------------------------------------------------
// Main: 296 persistent CTAs x 256 threads, dynamic tiles of 64b x 16m x 512d.
// 4-slot cp.async ring streams chunks (32 d) across tile boundaries with ONE
// __syncthreads per chunk. Thread tile 4b x 2m. bf16 HFMA2/HMUL2 inner loop;
// __log2f merge every 64 d. Partial log2-sums to g_part[dH].
// smem: xs 4 x (64 rows x 5 uint4, permuted rows, stride-5 anti-conflict)
//       cs 4 x (16 rows x 9 uint4, permuted rows)
// ---------------------------------------------------------------------------
__global__ void __launch_bounds__(256, 2) main_kernel() {
    extern __shared__ uint4 sm[];
    uint4* xs = sm;           // 4 stages x 320 uint4
    uint4* cs = sm + 1280;    // 4 stages x 144 uint4
    __shared__ int sh_t;

    const int t  = threadIdx.x;
    const int tx = t & 7;             // m-group (2 m each)
    const int ty = (t >> 3) & 15;     // b-group (4 b each)

    // fetch-role mappings
    const int xr = t >> 2, xq = t & 3;             // x dst: row 0..63, quad 0..3
    const int x_bl = (xr & 15) * 4 + (xr >> 4);    // b-local held by dst row xr
    const int cr = t >> 3, cu = t & 7;             // c dst (t<128): row 0..15, u 0..7
    const int c_ml = (cr & 7) * 2 + (cr >> 3);     // m-local held by dst row cr

    const uint32_t xs_base = (uint32_t)__cvta_generic_to_shared(xs);
    const uint32_t cs_base = (uint32_t)__cvta_generic_to_shared(cs);
    const uint32_t xdst = xs_base + (xr * 5 + xq) * 16;
    const uint32_t cdst = cs_base + (cr * 9 + cu) * 16;

    auto issue = [&](int tile, int ck, int slot) {
        if (tile < NT) {
            int dH = tile & 1, mT = (tile >> 1) & 15, bT = tile >> 5;
            const uint32_t* xsrc = g_xb + (size_t)(bT * 64 + x_bl) * (DD / 2)
                                  + dH * 256 + ck * 16 + xq * 4;
            cp16(xdst + slot * 320 * 16, xsrc);
            if (t < 128) {
                const uint32_t* csrc = g_cb + (size_t)(mT * 16 + c_ml) * DD
                                      + dH * 512 + ck * 32 + cu * 4;
                cp16(cdst + slot * 144 * 16, csrc);
            }
        }
        asm volatile("cp.async.commit_group;");
    };

    auto grab = [&]() -> int {
        __syncthreads();
        if (t == 0) sh_t = atomicAdd(&g_ctr, 1);
        __syncthreads();
        return sh_t;
    };

    int cur = blockIdx.x;     // < NT (296 < 1024)
    issue(cur, 0, 0);
    issue(cur, 1, 1);
    issue(cur, 2, 2);
    int nxt = grab();
    int slot = 3, cslot = 0;

    const uint32_t ONE2 = 0x3F803F80u;

    while (cur < NT) {
        __nv_bfloat162 prod[2][4];
        float acc[2][4];
#pragma unroll
        for (int jm = 0; jm < 2; jm++)
#pragma unroll
            for (int i = 0; i < 4; i++) { prod[jm][i] = asbf2(ONE2); acc[jm][i] = 0.0f; }

        for (int ck = 0; ck < CHUNKS; ck++) {
            asm volatile("cp.async.wait_group 2;");
            __syncthreads();
            // fetch 3 chunks ahead (crosses into tile nxt near the end)
            {
                int fck = ck + 3, ft = cur;
                if (fck >= CHUNKS) { fck -= CHUNKS; ft = nxt; }
                issue(ft, fck, slot);
                slot = (slot + 1) & 3;
            }
            const uint4* xb = xs + cslot * 320;
            const uint4* cb = cs + cslot * 144;
#pragma unroll
            for (int jq = 0; jq < 4; jq++) {          // 8 d per jq
                uint4 xv[4];
#pragma unroll
                for (int i = 0; i < 4; i++) xv[i] = xb[(i * 16 + ty) * 5 + jq];
#pragma unroll
                for (int jm = 0; jm < 2; jm++) {
                    uint4 c0 = cb[(jm * 8 + tx) * 9 + jq * 2];
                    uint4 c1 = cb[(jm * 8 + tx) * 9 + jq * 2 + 1];
#pragma unroll
                    for (int i = 0; i < 4; i++) {
                        __nv_bfloat162 l0 = __hfma2(asbf2(c0.x), asbf2(xv[i].x), asbf2(c0.y));
                        __nv_bfloat162 l1 = __hfma2(asbf2(c0.z), asbf2(xv[i].y), asbf2(c0.w));
                        __nv_bfloat162 l2 = __hfma2(asbf2(c1.x), asbf2(xv[i].z), asbf2(c1.y));
                        __nv_bfloat162 l3 = __hfma2(asbf2(c1.z), asbf2(xv[i].w), asbf2(c1.w));
                        prod[jm][i] = __hmul2(prod[jm][i],
                                              __hmul2(__hmul2(l0, l1), __hmul2(l2, l3)));
                    }
                }
            }
            cslot = (cslot + 1) & 3;
            if (ck & 1) {   // merge every 64 d
#pragma unroll
                for (int jm = 0; jm < 2; jm++)
#pragma unroll
                    for (int i = 0; i < 4; i++) {
                        uint32_t u = asu32(prod[jm][i]);
                        float hi = __uint_as_float(u & 0xFFFF0000u);
                        float lo = __uint_as_float(u << 16);
                        acc[jm][i] += __log2f(hi * lo);
                        prod[jm][i] = asbf2(ONE2);
                    }
            }
        }

        // epilogue: write 8 partials (float2 per i: m pair tx*2, tx*2+1)
        {
            int dH = cur & 1, mT = (cur >> 1) & 15, bT = cur >> 5;
            float* base = g_part[dH];
#pragma unroll
            for (int i = 0; i < 4; i++) {
                float2 v = make_float2(acc[0][i], acc[1][i]);
                *reinterpret_cast<float2*>(
                    base + (size_t)(bT * 64 + ty * 4 + i) * MM + mT * 16 + tx * 2) = v;
            }
        }
        cur = nxt;
        nxt = grab();
    }
    asm volatile("cp.async.wait_group 0;");
}

// ---------------------------------------------------------------------------
// Reduce: one warp per batch (2048 warps). comp = (p0+p1-1024)*ln2 + logw,
// then logsumexp over 256 m.
// ---------------------------------------------------------------------------
__global__ void reduce_kernel(float* __restrict__ out) {
    const float LN2 = 0.69314718055994531f;
    int w = (blockIdx.x << 4) + (threadIdx.x >> 5);
    int lane = threadIdx.x & 31;
    const float4* p0 = reinterpret_cast<const float4*>(g_part[0] + (size_t)w * MM) + lane * 2;
    const float4* p1 = reinterpret_cast<const float4*>(g_part[1] + (size_t)w * MM) + lane * 2;
    const float4* lw = reinterpret_cast<const float4*>(g_logw) + lane * 2;
    float v[8];
    float mx = -1e30f;
#pragma unroll
    for (int k = 0; k < 2; k++) {
        float4 a = p0[k], b = p1[k], l = lw[k];
        v[k*4+0] = (a.x + b.x - 1024.0f) * LN2 + l.x;
        v[k*4+1] = (a.y + b.y - 1024.0f) * LN2 + l.y;
        v[k*4+2] = (a.z + b.z - 1024.0f) * LN2 + l.z;
        v[k*4+3] = (a.w + b.w - 1024.0f) * LN2 + l.w;
#pragma unroll
        for (int j = 0; j < 4; j++) mx = fmaxf(mx, v[k*4+j]);
    }
#pragma unroll
    for (int o = 16; o > 0; o >>= 1) mx = fmaxf(mx, __shfl_xor_sync(0xFFFFFFFFu, mx, o));
    float s = 0.0f;
#pragma unroll
    for (int k = 0; k < 8; k++) s += __expf(v[k] - mx);
#pragma unroll
    for (int o = 16; o > 0; o >>= 1) s += __shfl_xor_sync(0xFFFFFFFFu, s, o);
    if (lane == 0) out[w] = mx + __logf(s);
}

extern "C" void kernel_launch(void* const* d_in, const int* in_sizes, int n_in,
                              void* d_out, int out_size) {
    const float* x = nullptr;
    const float* W = nullptr;
    const float* P = nullptr;
    for (int i = 0; i < n_in; i++) {
        if      (in_sizes[i] == BB * DD) x = (const float*)d_in[i];
        else if (in_sizes[i] == MM)      W = (const float*)d_in[i];
        else if (in_sizes[i] == MM * DD) P = (const float*)d_in[i];
    }

    prep_kernel<<<641, 256>>>(x, P, W);

    const int SMEM = (1280 + 576) * 16;   // 29,696 bytes per CTA
    cudaFuncSetAttribute(main_kernel, cudaFuncAttributeMaxDynamicSharedMemorySize, SMEM);
    main_kernel<<<NCTA, 256, SMEM>>>();

    reduce_kernel<<<BB / 16, 512>>>((float*)d_out);
}

// round 8
// speedup vs baseline: 1.6598x; 1.6598x over previous
#include <cuda_runtime.h>
#include <cuda_bf16.h>
#include <cstdint>
#include <cstring>

#define DD 1024
#define MM 256
#define BB 2048
#define NCH 8          // 8 chunks x 128 d
#define XSTG 1024      // uint4 per x stage (64 rows x 16)
#define CSTG 2112      // uint4 per c stage (64 rows x 33, odd stride)

// Device scratch (no allocations allowed)
__device__ __align__(16) uint32_t g_cb[MM * DD];          // per d-pair: {c1 bf16x2, c0 bf16x2}
__device__ __align__(16) uint32_t g_xb[BB * (DD / 2)];    // x as bf16x2 pairs
__device__ __align__(16) float g_logw[MM];
__device__ __align__(16) float g_comp[BB * MM];           // sum over d of log2(2*lik)

__device__ __forceinline__ __nv_bfloat162 asbf2(uint32_t u) {
    __nv_bfloat162 r; memcpy(&r, &u, 4); return r;
}
__device__ __forceinline__ uint32_t asu32(__nv_bfloat162 b) {
    uint32_t u; memcpy(&u, &b, 4); return u;
}
__device__ __forceinline__ void cp16(uint32_t dst, const void* src) {
    asm volatile("cp.async.ca.shared.global [%0], [%1], 16;" :: "r"(dst), "l"(src));
}

// ---------------------------------------------------------------------------
// Fused prep (MLP-8): blocks [0,256) x->bf16; [256,320) P->coefs; 320: logw.
// ---------------------------------------------------------------------------
__global__ void prep_kernel(const float* __restrict__ x,
                            const float* __restrict__ P,
                            const float* __restrict__ W) {
    int bk = blockIdx.x, t = threadIdx.x;
    if (bk < 256) {
        const float4* src = reinterpret_cast<const float4*>(x) + bk * 2048 + t;
        uint2* dst = reinterpret_cast<uint2*>(g_xb) + bk * 2048 + t;
        float4 v[8];
#pragma unroll
        for (int k = 0; k < 8; k++) v[k] = src[k * 256];
#pragma unroll
        for (int k = 0; k < 8; k++) {
            uint2 w;
            w.x = asu32(__floats2bfloat162_rn(v[k].x, v[k].y));
            w.y = asu32(__floats2bfloat162_rn(v[k].z, v[k].w));
            dst[k * 256] = w;
        }
    } else if (bk < 320) {
        int b2 = bk - 256;
        const float2* src = reinterpret_cast<const float2*>(P) + b2 * 2048 + t;
        uint2* dst = reinterpret_cast<uint2*>(g_cb) + b2 * 2048 + t;
        float2 v[8];
#pragma unroll
        for (int k = 0; k < 8; k++) v[k] = src[k * 256];
#pragma unroll
        for (int k = 0; k < 8; k++) {
            float c0a = 2.0f / (1.0f + __expf(v[k].x));   // 2*(1-p)
            float c0b = 2.0f / (1.0f + __expf(v[k].y));
            float c1a = 2.0f - 2.0f * c0a;                // 2*(2p-1)
            float c1b = 2.0f - 2.0f * c0b;
            uint2 w;
            w.x = asu32(__floats2bfloat162_rn(c1a, c1b));
            w.y = asu32(__floats2bfloat162_rn(c0a, c0b));
            dst[k * 256] = w;
        }
    } else {
        __shared__ float sh[MM];
        float w = W[t];
        sh[t] = w;
        __syncthreads();
        for (int s = MM / 2; s > 0; s >>= 1) {
            if (t < s) sh[t] = fmaxf(sh[t], sh[t + s]);
            __syncthreads();
        }
        float mx = sh[0];
        __syncthreads();
        sh[t] = expf(w - mx);
        __syncthreads();
        for (int s = MM / 2; s > 0; s >>= 1) {
            if (t < s) sh[t] += sh[t + s];
            __syncthreads();
        }
        g_logw[t] = w - (mx + logf(sh[0]));
    }
}

// ---------------------------------------------------------------------------
// Main: block 64b x 64m, 512 threads = 16(tx,m) x 16(ty,b) x 2(tz,d-split),
// thread tile 4b x 4m over half of each 128-d chunk. 3-stage cp.async ring,
// ONE __syncthreads per chunk. bf16 HFMA2/HMUL2 inner; __log2f merge per
// chunk (64 d per accumulator).
// smem: xs 3 x (64 rows x 16 uint4)   -- broadcast reads
//       cs 3 x (64 rows x 33 uint4)   -- odd stride, conflict-free LDS.128
// ---------------------------------------------------------------------------
__global__ void __launch_bounds__(512, 1) main_kernel() {
    extern __shared__ uint4 sm[];
    uint4* xs = sm;                // 3 stages x XSTG
    uint4* cs = sm + 3 * XSTG;     // 3 stages x CSTG

    const int t  = threadIdx.x;
    const int tx = t & 15;
    const int ty = (t >> 4) & 15;
    const int tz = t >> 8;
    const int bBase = blockIdx.x * 64;
    const int mBase = blockIdx.y * 64;

    // fetch mappings: rows 0..63, 8 quads covered per thread-op set
    const int xr = t >> 3, xq = t & 7;
    const uint32_t* xsrc = g_xb + (size_t)(bBase + xr) * (DD / 2) + xq * 4;
    const uint32_t* csrc = g_cb + (size_t)(mBase + xr) * DD + xq * 4;
    const uint32_t xd = (uint32_t)__cvta_generic_to_shared(&xs[xr * 16 + xq]);
    const uint32_t cd = (uint32_t)__cvta_generic_to_shared(&cs[xr * 33 + xq]);

    auto issue = [&](int ck, int slot) {
        const uint32_t* xp = xsrc + ck * 64;          // 128 d = 64 uint32 per row
        uint32_t xb = xd + slot * XSTG * 16;
        cp16(xb,          xp);
        cp16(xb + 8 * 16, xp + 32);
        const uint32_t* cp = csrc + ck * 128;         // 128 d = 128 uint32 per row
        uint32_t cb = cd + slot * CSTG * 16;
        cp16(cb,           cp);
        cp16(cb + 8 * 16,  cp + 32);
        cp16(cb + 16 * 16, cp + 64);
        cp16(cb + 24 * 16, cp + 96);
        asm volatile("cp.async.commit_group;");
    };

    issue(0, 0);
    issue(1, 1);

    const uint32_t ONE2 = 0x3F803F80u;   // bf16x2 {1.0, 1.0}
    float acc[4][4];
#pragma unroll
    for (int i = 0; i < 4; i++)
#pragma unroll
        for (int jm = 0; jm < 4; jm++) acc[i][jm] = 0.0f;

    for (int ck = 0; ck < NCH; ck++) {
        asm volatile("cp.async.wait_group 1;");
        __syncthreads();
        if (ck + 2 < NCH) issue(ck + 2, (ck + 2) % 3);
        else asm volatile("cp.async.commit_group;");

        const int slot = ck % 3;
        const uint4* xb = xs + slot * XSTG + ty * 16 + tz * 8;
        const uint4* cb = cs + slot * CSTG + tx * 33 + tz * 16;

        __nv_bfloat162 prod[4][4];
#pragma unroll
        for (int i = 0; i < 4; i++)
#pragma unroll
            for (int jm = 0; jm < 4; jm++) prod[i][jm] = asbf2(ONE2);

#pragma unroll
        for (int jq = 0; jq < 8; jq++) {          // 8 d per jq (per tz half)
            uint4 xv[4];
#pragma unroll
            for (int i = 0; i < 4; i++) xv[i] = xb[i * 16 * 16 + jq];
#pragma unroll
            for (int jm = 0; jm < 4; jm++) {
                uint4 c0 = cb[jm * 16 * 33 + jq * 2];
                uint4 c1 = cb[jm * 16 * 33 + jq * 2 + 1];
#pragma unroll
                for (int i = 0; i < 4; i++) {
                    __nv_bfloat162 l0 = __hfma2(asbf2(c0.x), asbf2(xv[i].x), asbf2(c0.y));
                    __nv_bfloat162 l1 = __hfma2(asbf2(c0.z), asbf2(xv[i].y), asbf2(c0.w));
                    __nv_bfloat162 l2 = __hfma2(asbf2(c1.x), asbf2(xv[i].z), asbf2(c1.y));
                    __nv_bfloat162 l3 = __hfma2(asbf2(c1.z), asbf2(xv[i].w), asbf2(c1.w));
                    prod[i][jm] = __hmul2(prod[i][jm],
                                          __hmul2(__hmul2(l0, l1), __hmul2(l2, l3)));
                }
            }
        }
        // merge: this chunk contributed 64 d per accumulator (scaled x2: safe)
#pragma unroll
        for (int i = 0; i < 4; i++)
#pragma unroll
            for (int jm = 0; jm < 4; jm++) {
                uint32_t u = asu32(prod[i][jm]);
                float hi = __uint_as_float(u & 0xFFFF0000u);
                float lo = __uint_as_float(u << 16);
                acc[i][jm] += __log2f(hi * lo);
            }
    }

    asm volatile("cp.async.wait_group 0;");
    __syncthreads();
    // combine tz halves through smem (stride 17 floats: no bank conflicts)
    float* sh = (float*)sm;
    const int tid256 = t & 255;
    if (tz == 1) {
#pragma unroll
        for (int i = 0; i < 4; i++)
#pragma unroll
            for (int jm = 0; jm < 4; jm++)
                sh[tid256 * 17 + i * 4 + jm] = acc[i][jm];
    }
    __syncthreads();
    if (tz == 0) {
#pragma unroll
        for (int i = 0; i < 4; i++)
#pragma unroll
            for (int jm = 0; jm < 4; jm++) {
                float a = acc[i][jm] + sh[tid256 * 17 + i * 4 + jm];
                g_comp[(size_t)(bBase + ty + 16 * i) * MM + (mBase + tx + 16 * jm)] = a;
            }
    }
}

// ---------------------------------------------------------------------------
// Reduce: one warp per batch. comp_ll = (acc2 - 1024)*ln2 + logw, then
// logsumexp over 256 components.
// ---------------------------------------------------------------------------
__global__ void reduce_kernel(float* __restrict__ out) {
    const float LN2 = 0.69314718055994531f;
    int w = (blockIdx.x << 4) + (threadIdx.x >> 5);
    int lane = threadIdx.x & 31;
    const float4* cp4 = reinterpret_cast<const float4*>(g_comp + (size_t)w * MM) + lane * 2;
    const float4* lw4 = reinterpret_cast<const float4*>(g_logw) + lane * 2;
    float v[8];
    float mx = -1e30f;
#pragma unroll
    for (int k = 0; k < 2; k++) {
        float4 c = cp4[k];
        float4 l = lw4[k];
        v[k*4+0] = (c.x - 1024.0f) * LN2 + l.x;
        v[k*4+1] = (c.y - 1024.0f) * LN2 + l.y;
        v[k*4+2] = (c.z - 1024.0f) * LN2 + l.z;
        v[k*4+3] = (c.w - 1024.0f) * LN2 + l.w;
#pragma unroll
        for (int j = 0; j < 4; j++) mx = fmaxf(mx, v[k*4+j]);
    }
#pragma unroll
    for (int o = 16; o > 0; o >>= 1) mx = fmaxf(mx, __shfl_xor_sync(0xFFFFFFFFu, mx, o));
    float s = 0.0f;
#pragma unroll
    for (int k = 0; k < 8; k++) s += __expf(v[k] - mx);
#pragma unroll
    for (int o = 16; o > 0; o >>= 1) s += __shfl_xor_sync(0xFFFFFFFFu, s, o);
    if (lane == 0) out[w] = mx + __logf(s);
}

extern "C" void kernel_launch(void* const* d_in, const int* in_sizes, int n_in,
                              void* d_out, int out_size) {
    const float* x = nullptr;
    const float* W = nullptr;
    const float* P = nullptr;
    for (int i = 0; i < n_in; i++) {
        if      (in_sizes[i] == BB * DD) x = (const float*)d_in[i];
        else if (in_sizes[i] == MM)      W = (const float*)d_in[i];
        else if (in_sizes[i] == MM * DD) P = (const float*)d_in[i];
    }

    prep_kernel<<<321, 256>>>(x, P, W);

    const int SMEM = 3 * (XSTG + CSTG) * 16;   // 150,528 bytes
    cudaFuncSetAttribute(main_kernel, cudaFuncAttributeMaxDynamicSharedMemorySize, SMEM);
    dim3 grid(BB / 64, MM / 64);
    main_kernel<<<grid, 512, SMEM>>>();

    reduce_kernel<<<BB / 16, 512>>>((float*)d_out);
}